// round 1
// baseline (speedup 1.0000x reference)
#include <cuda_runtime.h>
#include <cstdint>

#define BB 8
#define CC 512
#define NN 4096
#define CQ 80

// Scratch (device globals — allocation-guard safe)
__device__ float g_q[(size_t)BB * CQ * NN];                 // 10.5 MB
__device__ float g_k[(size_t)BB * CQ * NN];                 // 10.5 MB
__device__ float g_v[(size_t)BB * CC * NN];                 // 67 MB
__device__ float g_attn[(size_t)BB * NN * NN];              // 512 MB

// ---------------------------------------------------------------------------
// Projection: Y[b][o,n] = relu( scale[o] * (sum_c W[o,c] * x[b,c,n]) + bias[o] )
// W: [O, C] row-major (K-contig).  x: [B, C, N] (N-contig).
// 128x128 tile, K-chunk 16, 256 threads, 8x8 per thread.
// which: 0 -> g_q, 1 -> g_k, 2 -> g_v
// ---------------------------------------------------------------------------
__global__ __launch_bounds__(256, 2)
void proj_kernel(const float* __restrict__ W, const float* __restrict__ x,
                 const float* __restrict__ scale, const float* __restrict__ bias,
                 int which, int O)
{
    __shared__ float As[16][136];  // As[k][m]
    __shared__ float Bs[16][136];  // Bs[k][n]

    const int b  = blockIdx.z;
    const int m0 = blockIdx.x * 128;
    const int n0 = blockIdx.y * 128;
    const int tid = threadIdx.x;
    const int tx = tid & 15;        // n dimension
    const int ty = tid >> 4;        // m dimension

    const float* xb = x + (size_t)b * CC * NN;
    float* Y = (which == 0) ? g_q : (which == 1) ? g_k : g_v;
    float* Yb = Y + (size_t)b * O * NN;

    float acc[8][8];
#pragma unroll
    for (int u = 0; u < 8; u++)
#pragma unroll
        for (int v = 0; v < 8; v++) acc[u][v] = 0.f;

    for (int k0 = 0; k0 < CC; k0 += 16) {
        // Load A tile: W[m0+m][k0+kk] -> As[kk][m]  (transpose-scatter)
        {
            int m  = tid >> 1;
            int kk = (tid & 1) * 8;
            float4 v0, v1;
            if (m0 + m < O) {
                const float* p = W + (size_t)(m0 + m) * CC + k0 + kk;
                v0 = *(const float4*)p;
                v1 = *(const float4*)(p + 4);
            } else {
                v0 = make_float4(0.f, 0.f, 0.f, 0.f);
                v1 = v0;
            }
            As[kk + 0][m] = v0.x; As[kk + 1][m] = v0.y;
            As[kk + 2][m] = v0.z; As[kk + 3][m] = v0.w;
            As[kk + 4][m] = v1.x; As[kk + 5][m] = v1.y;
            As[kk + 6][m] = v1.z; As[kk + 7][m] = v1.w;
        }
        // Load B tile: x[k0+kk][n0+nn] -> Bs[kk][nn]  (coalesced)
        {
            int kk = tid >> 4;
            int nn = (tid & 15) * 8;
            const float* p = xb + (size_t)(k0 + kk) * NN + n0 + nn;
            float4 v0 = *(const float4*)p;
            float4 v1 = *(const float4*)(p + 4);
            *(float4*)&Bs[kk][nn]     = v0;
            *(float4*)&Bs[kk][nn + 4] = v1;
        }
        __syncthreads();

#pragma unroll
        for (int kk = 0; kk < 16; kk++) {
            float4 a0 = *(float4*)&As[kk][ty * 8];
            float4 a1 = *(float4*)&As[kk][ty * 8 + 4];
            float4 b0 = *(float4*)&Bs[kk][tx * 8];
            float4 b1 = *(float4*)&Bs[kk][tx * 8 + 4];
            float a[8] = {a0.x, a0.y, a0.z, a0.w, a1.x, a1.y, a1.z, a1.w};
            float bb[8] = {b0.x, b0.y, b0.z, b0.w, b1.x, b1.y, b1.z, b1.w};
#pragma unroll
            for (int u = 0; u < 8; u++)
#pragma unroll
                for (int v = 0; v < 8; v++)
                    acc[u][v] = fmaf(a[u], bb[v], acc[u][v]);
        }
        __syncthreads();
    }

#pragma unroll
    for (int u = 0; u < 8; u++) {
        int m = m0 + ty * 8 + u;
        if (m < O) {
            float s = scale[m], bi = bias[m];
#pragma unroll
            for (int v = 0; v < 8; v++) {
                int n = n0 + tx * 8 + v;
                float r = fmaf(acc[u][v], s, bi);
                Yb[(size_t)m * NN + n] = r > 0.f ? r : 0.f;
            }
        }
    }
}

// ---------------------------------------------------------------------------
// Energy: E[b][i,j] = sum_c q[b][c,i] * k[b][c,j].  q,k: [B, 80, N].
// A[m,k] = q[k*N + m] (M-contig), B[n,k] = k[k*N + n] (N-contig). K=80.
// ---------------------------------------------------------------------------
__global__ __launch_bounds__(256, 2)
void energy_kernel()
{
    __shared__ float As[16][136];
    __shared__ float Bs[16][136];

    const int b  = blockIdx.z;
    const int m0 = blockIdx.x * 128;   // i
    const int n0 = blockIdx.y * 128;   // j
    const int tid = threadIdx.x;
    const int tx = tid & 15;
    const int ty = tid >> 4;

    const float* qb = g_q + (size_t)b * CQ * NN;
    const float* kb = g_k + (size_t)b * CQ * NN;
    float* Eb = g_attn + (size_t)b * NN * NN;

    float acc[8][8];
#pragma unroll
    for (int u = 0; u < 8; u++)
#pragma unroll
        for (int v = 0; v < 8; v++) acc[u][v] = 0.f;

    for (int k0 = 0; k0 < CQ; k0 += 16) {
        {
            int kk = tid >> 4;
            int mm = (tid & 15) * 8;
            const float* p = qb + (size_t)(k0 + kk) * NN + m0 + mm;
            float4 v0 = *(const float4*)p;
            float4 v1 = *(const float4*)(p + 4);
            *(float4*)&As[kk][mm]     = v0;
            *(float4*)&As[kk][mm + 4] = v1;
            const float* p2 = kb + (size_t)(k0 + kk) * NN + n0 + mm;
            float4 w0 = *(const float4*)p2;
            float4 w1 = *(const float4*)(p2 + 4);
            *(float4*)&Bs[kk][mm]     = w0;
            *(float4*)&Bs[kk][mm + 4] = w1;
        }
        __syncthreads();

#pragma unroll
        for (int kk = 0; kk < 16; kk++) {
            float4 a0 = *(float4*)&As[kk][ty * 8];
            float4 a1 = *(float4*)&As[kk][ty * 8 + 4];
            float4 b0 = *(float4*)&Bs[kk][tx * 8];
            float4 b1 = *(float4*)&Bs[kk][tx * 8 + 4];
            float a[8] = {a0.x, a0.y, a0.z, a0.w, a1.x, a1.y, a1.z, a1.w};
            float bb[8] = {b0.x, b0.y, b0.z, b0.w, b1.x, b1.y, b1.z, b1.w};
#pragma unroll
            for (int u = 0; u < 8; u++)
#pragma unroll
                for (int v = 0; v < 8; v++)
                    acc[u][v] = fmaf(a[u], bb[v], acc[u][v]);
        }
        __syncthreads();
    }

#pragma unroll
    for (int u = 0; u < 8; u++) {
        int m = m0 + ty * 8 + u;
#pragma unroll
        for (int v = 0; v < 8; v += 4) {
            int n = n0 + tx * 8 + v;
            float4 o = make_float4(acc[u][v], acc[u][v + 1], acc[u][v + 2], acc[u][v + 3]);
            *(float4*)&Eb[(size_t)m * NN + n] = o;
        }
    }
}

// ---------------------------------------------------------------------------
// Softmax over rows of g_attn (in place). One block of 256 threads per row.
// Values held in registers: 1 read + 1 write of 512 MB total.
// ---------------------------------------------------------------------------
__global__ __launch_bounds__(256)
void softmax_kernel()
{
    __shared__ float red[8];
    const size_t row = blockIdx.x;
    float* p = g_attn + row * (size_t)NN;
    const int tid = threadIdx.x;
    const int lane = tid & 31;
    const int wid  = tid >> 5;

    float vals[16];
    float mx = -1e30f;
#pragma unroll
    for (int j = 0; j < 16; j++) {
        vals[j] = p[tid + j * 256];
        mx = fmaxf(mx, vals[j]);
    }
#pragma unroll
    for (int off = 16; off > 0; off >>= 1)
        mx = fmaxf(mx, __shfl_xor_sync(0xffffffffu, mx, off));
    if (lane == 0) red[wid] = mx;
    __syncthreads();
    if (tid == 0) {
        float m = red[0];
#pragma unroll
        for (int i = 1; i < 8; i++) m = fmaxf(m, red[i]);
        red[0] = m;
    }
    __syncthreads();
    mx = red[0];
    __syncthreads();

    float sum = 0.f;
#pragma unroll
    for (int j = 0; j < 16; j++) {
        vals[j] = __expf(vals[j] - mx);
        sum += vals[j];
    }
#pragma unroll
    for (int off = 16; off > 0; off >>= 1)
        sum += __shfl_xor_sync(0xffffffffu, sum, off);
    if (lane == 0) red[wid] = sum;
    __syncthreads();
    if (tid == 0) {
        float s = 0.f;
#pragma unroll
        for (int i = 0; i < 8; i++) s += red[i];
        red[0] = s;
    }
    __syncthreads();
    const float inv = 1.f / red[0];

#pragma unroll
    for (int j = 0; j < 16; j++)
        p[tid + j * 256] = vals[j] * inv;
}

// ---------------------------------------------------------------------------
// Out: O[b][c,i] = sum_j v[b][c,j] * attn[b][i,j];  result = gamma[c,i]*O + x.
// A[m,k] = v[c,j] (K-contig), B[n,k] = attn[i,j] (K-contig). TN GEMM.
// ---------------------------------------------------------------------------
__global__ __launch_bounds__(256, 2)
void out_kernel(const float* __restrict__ gamma, const float* __restrict__ x,
                float* __restrict__ out)
{
    __shared__ float As[16][136];
    __shared__ float Bs[16][136];

    const int b  = blockIdx.z;
    const int m0 = blockIdx.x * 128;   // c
    const int n0 = blockIdx.y * 128;   // i
    const int tid = threadIdx.x;
    const int tx = tid & 15;
    const int ty = tid >> 4;

    const float* vb = g_v + (size_t)b * CC * NN;
    const float* ab = g_attn + (size_t)b * NN * NN;

    float acc[8][8];
#pragma unroll
    for (int u = 0; u < 8; u++)
#pragma unroll
        for (int v = 0; v < 8; v++) acc[u][v] = 0.f;

    const int m = tid >> 1;
    const int kk8 = (tid & 1) * 8;

    for (int k0 = 0; k0 < NN; k0 += 16) {
        // A: v[m0+m][k0+kk] -> As[kk][m]
        {
            const float* p = vb + (size_t)(m0 + m) * NN + k0 + kk8;
            float4 v0 = *(const float4*)p;
            float4 v1 = *(const float4*)(p + 4);
            As[kk8 + 0][m] = v0.x; As[kk8 + 1][m] = v0.y;
            As[kk8 + 2][m] = v0.z; As[kk8 + 3][m] = v0.w;
            As[kk8 + 4][m] = v1.x; As[kk8 + 5][m] = v1.y;
            As[kk8 + 6][m] = v1.z; As[kk8 + 7][m] = v1.w;
        }
        // B: attn[n0+m][k0+kk] -> Bs[kk][n]
        {
            const float* p = ab + (size_t)(n0 + m) * NN + k0 + kk8;
            float4 v0 = *(const float4*)p;
            float4 v1 = *(const float4*)(p + 4);
            Bs[kk8 + 0][m] = v0.x; Bs[kk8 + 1][m] = v0.y;
            Bs[kk8 + 2][m] = v0.z; Bs[kk8 + 3][m] = v0.w;
            Bs[kk8 + 4][m] = v1.x; Bs[kk8 + 5][m] = v1.y;
            Bs[kk8 + 6][m] = v1.z; Bs[kk8 + 7][m] = v1.w;
        }
        __syncthreads();

#pragma unroll
        for (int kk = 0; kk < 16; kk++) {
            float4 a0 = *(float4*)&As[kk][ty * 8];
            float4 a1 = *(float4*)&As[kk][ty * 8 + 4];
            float4 b0 = *(float4*)&Bs[kk][tx * 8];
            float4 b1 = *(float4*)&Bs[kk][tx * 8 + 4];
            float a[8] = {a0.x, a0.y, a0.z, a0.w, a1.x, a1.y, a1.z, a1.w};
            float bb[8] = {b0.x, b0.y, b0.z, b0.w, b1.x, b1.y, b1.z, b1.w};
#pragma unroll
            for (int u = 0; u < 8; u++)
#pragma unroll
                for (int v = 0; v < 8; v++)
                    acc[u][v] = fmaf(a[u], bb[v], acc[u][v]);
        }
        __syncthreads();
    }

#pragma unroll
    for (int u = 0; u < 8; u++) {
        int c = m0 + ty * 8 + u;
#pragma unroll
        for (int v = 0; v < 8; v++) {
            int i = n0 + tx * 8 + v;
            size_t gi = (size_t)c * NN + i;
            size_t bi = (size_t)b * CC * NN + gi;
            out[bi] = fmaf(gamma[gi], acc[u][v], x[bi]);
        }
    }
}

// ---------------------------------------------------------------------------
extern "C" void kernel_launch(void* const* d_in, const int* in_sizes, int n_in,
                              void* d_out, int out_size)
{
    const float* x     = (const float*)d_in[0];
    const float* Wq    = (const float*)d_in[1];
    const float* Wk    = (const float*)d_in[2];
    const float* Wv    = (const float*)d_in[3];
    const float* sq    = (const float*)d_in[4];
    const float* bq    = (const float*)d_in[5];
    const float* sk    = (const float*)d_in[6];
    const float* bk    = (const float*)d_in[7];
    const float* sv    = (const float*)d_in[8];
    const float* bv    = (const float*)d_in[9];
    const float* gamma = (const float*)d_in[10];
    float* out = (float*)d_out;

    dim3 blk(256);

    // Projections
    proj_kernel<<<dim3(1, NN / 128, BB), blk>>>(Wq, x, sq, bq, 0, CQ);
    proj_kernel<<<dim3(1, NN / 128, BB), blk>>>(Wk, x, sk, bk, 1, CQ);
    proj_kernel<<<dim3(CC / 128, NN / 128, BB), blk>>>(Wv, x, sv, bv, 2, CC);

    // Energy
    energy_kernel<<<dim3(NN / 128, NN / 128, BB), blk>>>();

    // Softmax (in place on g_attn)
    softmax_kernel<<<BB * NN, blk>>>();

    // Out GEMM + fused gamma*out + x
    out_kernel<<<dim3(CC / 128, NN / 128, BB), blk>>>(gamma, x, out);
}

// round 3
// speedup vs baseline: 3.7365x; 3.7365x over previous
#include <cuda_runtime.h>
#include <cuda_bf16.h>
#include <cstdint>

#define BB 8
#define CC 512
#define NN 4096
#define CQ 80
#define NP 128   // CQ padded to 128 for bf16 MMA K

// ---------------- scratch (device globals; allocation-guard safe) ----------
__device__ float          g_energy[(size_t)BB * NN * NN];   // 512 MB fp32
__device__ __nv_bfloat16  g_attnb [(size_t)BB * NN * NN];   // 256 MB bf16
__device__ __nv_bfloat16  g_vb    [(size_t)BB * CC * NN];   // 64 MB
__device__ __nv_bfloat16  g_qT    [(size_t)BB * NN * NP];   // 8 MB  [b][n][c], zero-padded
__device__ __nv_bfloat16  g_kT    [(size_t)BB * NN * NP];   // 8 MB

// ---------------- helpers ---------------------------------------------------
__device__ __forceinline__ uint32_t smem_u32(const void* p) {
    uint32_t a;
    asm("{ .reg .u64 t; cvta.to.shared.u64 t, %1; cvt.u32.u64 %0, t; }" : "=r"(a) : "l"(p));
    return a;
}
__device__ __forceinline__ void ldsm4(uint32_t& r0, uint32_t& r1, uint32_t& r2, uint32_t& r3,
                                      uint32_t addr) {
    asm volatile("ldmatrix.sync.aligned.m8n8.x4.shared.b16 {%0,%1,%2,%3}, [%4];"
                 : "=r"(r0), "=r"(r1), "=r"(r2), "=r"(r3) : "r"(addr));
}
__device__ __forceinline__ void mma16816(float* c, uint32_t a0, uint32_t a1, uint32_t a2,
                                         uint32_t a3, uint32_t b0, uint32_t b1) {
    asm volatile("mma.sync.aligned.m16n8k16.row.col.f32.bf16.bf16.f32 "
                 "{%0,%1,%2,%3},{%4,%5,%6,%7},{%8,%9},{%0,%1,%2,%3};"
                 : "+f"(c[0]), "+f"(c[1]), "+f"(c[2]), "+f"(c[3])
                 : "r"(a0), "r"(a1), "r"(a2), "r"(a3), "r"(b0), "r"(b1));
}
#define CP_ASYNC16(dst, src) \
    asm volatile("cp.async.cg.shared.global [%0], [%1], 16;" :: "r"(dst), "l"(src))
#define CP_COMMIT() asm volatile("cp.async.commit_group;" ::: "memory")
#define CP_WAIT1()  asm volatile("cp.async.wait_group 1;" ::: "memory")
#define CP_WAIT0()  asm volatile("cp.async.wait_group 0;" ::: "memory")

// smem tile: 128 rows x 64 bf16 (128B rows). chunk c in [0,8) of 16B; SW128-style xor.
#define SW(r, c) ((uint32_t)(((r) * 128) + ((((c) ^ ((r) & 7))) * 16)))

// ---------------------------------------------------------------------------
// Shared 128x128 bf16 GEMM body.  C[128,128] += A[128,K] * B[128,K]^T
// A row-major k-contig (Ag, aStride uint4/row), B row-major k-contig.
// BK=64, cp.async double buffer (64KB), 8 warps of 64x32, m16n8k16 frags.
// ---------------------------------------------------------------------------
template <int NK>
__device__ __forceinline__ void gemm128x128(uint32_t sb, const uint4* __restrict__ Ag,
                                            const uint4* __restrict__ Bg, int aStride,
                                            int bStride, int m0, int n0,
                                            float (&acc)[4][4][4]) {
    const int tid = threadIdx.x;
    const int lane = tid & 31, wid = tid >> 5;
    const int wm = wid >> 2, wn = wid & 3;
    const int lr = tid >> 3, lc = tid & 7;

    // frag lane rows
    int a_r[4], b_r[2];
#pragma unroll
    for (int mt = 0; mt < 4; mt++) a_r[mt] = wm * 64 + mt * 16 + ((lane >> 3) & 1) * 8 + (lane & 7);
#pragma unroll
    for (int p = 0; p < 2; p++) b_r[p] = wn * 32 + p * 16 + ((lane >> 4) & 1) * 8 + (lane & 7);
    const int a_kc = (lane >> 4) & 1;
    const int b_kc = (lane >> 3) & 1;

    // prologue: issue tile 0
    {
        uint32_t dA = sb, dB = sb + 16384;
#pragma unroll
        for (int p = 0; p < 4; p++) {
            int r = p * 32 + lr;
            CP_ASYNC16(dA + SW(r, lc), (const void*)(Ag + (size_t)(m0 + r) * aStride + lc));
            CP_ASYNC16(dB + SW(r, lc), (const void*)(Bg + (size_t)(n0 + r) * bStride + lc));
        }
        CP_COMMIT();
    }

#pragma unroll 1
    for (int t = 0; t < NK; t++) {
        if (t + 1 < NK) {
            uint32_t dA = sb + ((t + 1) & 1) * 32768, dB = dA + 16384;
#pragma unroll
            for (int p = 0; p < 4; p++) {
                int r = p * 32 + lr;
                CP_ASYNC16(dA + SW(r, lc),
                           (const void*)(Ag + (size_t)(m0 + r) * aStride + (t + 1) * 8 + lc));
                CP_ASYNC16(dB + SW(r, lc),
                           (const void*)(Bg + (size_t)(n0 + r) * bStride + (t + 1) * 8 + lc));
            }
            CP_COMMIT();
            CP_WAIT1();
        } else {
            CP_WAIT0();
        }
        __syncthreads();

        const uint32_t Asb = sb + (t & 1) * 32768;
        const uint32_t Bsb = Asb + 16384;
#pragma unroll
        for (int ks = 0; ks < 4; ks++) {
            uint32_t aF[4][4], bF[2][4];
#pragma unroll
            for (int mt = 0; mt < 4; mt++)
                ldsm4(aF[mt][0], aF[mt][1], aF[mt][2], aF[mt][3],
                      Asb + SW(a_r[mt], ks * 2 + a_kc));
#pragma unroll
            for (int p = 0; p < 2; p++)
                ldsm4(bF[p][0], bF[p][1], bF[p][2], bF[p][3],
                      Bsb + SW(b_r[p], ks * 2 + b_kc));
#pragma unroll
            for (int mt = 0; mt < 4; mt++) {
                mma16816(acc[mt][0], aF[mt][0], aF[mt][1], aF[mt][2], aF[mt][3], bF[0][0], bF[0][1]);
                mma16816(acc[mt][1], aF[mt][0], aF[mt][1], aF[mt][2], aF[mt][3], bF[0][2], bF[0][3]);
                mma16816(acc[mt][2], aF[mt][0], aF[mt][1], aF[mt][2], aF[mt][3], bF[1][0], bF[1][1]);
                mma16816(acc[mt][3], aF[mt][0], aF[mt][1], aF[mt][2], aF[mt][3], bF[1][2], bF[1][3]);
            }
        }
        __syncthreads();
    }
}

// ---------------------------------------------------------------------------
// proj_qk: 80-ch bottleneck (fp32 compute), writes TRANSPOSED zero-padded bf16
// qT[b][n][0..127].  grid (NN/128, BB), 256 threads.
// ---------------------------------------------------------------------------
__global__ __launch_bounds__(256, 2)
void proj_qk_kernel(const float* __restrict__ W, const float* __restrict__ x,
                    const float* __restrict__ scale, const float* __restrict__ bias,
                    int which)
{
    __shared__ union {
        struct { float As[16][136]; float Bs[16][136]; } ab;
        __nv_bfloat16 st[128][136];
    } sm;

    const int b  = blockIdx.y;
    const int n0 = blockIdx.x * 128;
    const int tid = threadIdx.x;
    const int tx = tid & 15;
    const int ty = tid >> 4;

    const float* xb = x + (size_t)b * CC * NN;

    float acc[8][8];
#pragma unroll
    for (int u = 0; u < 8; u++)
#pragma unroll
        for (int v = 0; v < 8; v++) acc[u][v] = 0.f;

    for (int k0 = 0; k0 < CC; k0 += 16) {
        {
            int m  = tid >> 1;
            int kk = (tid & 1) * 8;
            float4 v0, v1;
            if (m < CQ) {
                const float* p = W + (size_t)m * CC + k0 + kk;
                v0 = *(const float4*)p;
                v1 = *(const float4*)(p + 4);
            } else {
                v0 = make_float4(0.f, 0.f, 0.f, 0.f);
                v1 = v0;
            }
            sm.ab.As[kk + 0][m] = v0.x; sm.ab.As[kk + 1][m] = v0.y;
            sm.ab.As[kk + 2][m] = v0.z; sm.ab.As[kk + 3][m] = v0.w;
            sm.ab.As[kk + 4][m] = v1.x; sm.ab.As[kk + 5][m] = v1.y;
            sm.ab.As[kk + 6][m] = v1.z; sm.ab.As[kk + 7][m] = v1.w;
        }
        {
            int kk = tid >> 4;
            int nn = (tid & 15) * 8;
            const float* p = xb + (size_t)(k0 + kk) * NN + n0 + nn;
            *(float4*)&sm.ab.Bs[kk][nn]     = *(const float4*)p;
            *(float4*)&sm.ab.Bs[kk][nn + 4] = *(const float4*)(p + 4);
        }
        __syncthreads();
#pragma unroll
        for (int kk = 0; kk < 16; kk++) {
            float4 a0 = *(float4*)&sm.ab.As[kk][ty * 8];
            float4 a1 = *(float4*)&sm.ab.As[kk][ty * 8 + 4];
            float4 b0 = *(float4*)&sm.ab.Bs[kk][tx * 8];
            float4 b1 = *(float4*)&sm.ab.Bs[kk][tx * 8 + 4];
            float a[8] = {a0.x, a0.y, a0.z, a0.w, a1.x, a1.y, a1.z, a1.w};
            float bb[8] = {b0.x, b0.y, b0.z, b0.w, b1.x, b1.y, b1.z, b1.w};
#pragma unroll
            for (int u = 0; u < 8; u++)
#pragma unroll
                for (int v = 0; v < 8; v++)
                    acc[u][v] = fmaf(a[u], bb[v], acc[u][v]);
        }
        __syncthreads();
    }

#pragma unroll
    for (int u = 0; u < 8; u++) {
        int c = ty * 8 + u;
        float s = 0.f, bi = 0.f;
        if (c < CQ) { s = scale[c]; bi = bias[c]; }
#pragma unroll
        for (int v = 0; v < 8; v++) {
            float r = fmaf(acc[u][v], s, bi);
            r = r > 0.f ? r : 0.f;
            sm.st[tx * 8 + v][c] = (c < CQ) ? __float2bfloat16(r) : __float2bfloat16(0.f);
        }
    }
    __syncthreads();

    __nv_bfloat16* qT = (which ? g_kT : g_qT) + (size_t)b * NN * NP;
#pragma unroll
    for (int k = 0; k < 8; k++) {
        int idx = k * 256 + tid;
        int r = idx >> 4, j = idx & 15;
        uint4 val = *(uint4*)&sm.st[r][j * 8];
        ((uint4*)qT)[(size_t)(n0 + r) * (NP / 8) + j] = val;
    }
}

// ---------------------------------------------------------------------------
// proj_v: full C=512 channels, fp32 GEMM, bf16 output [b][c][n].
// ---------------------------------------------------------------------------
__global__ __launch_bounds__(256, 2)
void proj_v_kernel(const float* __restrict__ W, const float* __restrict__ x,
                   const float* __restrict__ scale, const float* __restrict__ bias)
{
    __shared__ float As[16][136];
    __shared__ float Bs[16][136];

    const int b  = blockIdx.z;
    const int m0 = blockIdx.x * 128;
    const int n0 = blockIdx.y * 128;
    const int tid = threadIdx.x;
    const int tx = tid & 15;
    const int ty = tid >> 4;

    const float* xb = x + (size_t)b * CC * NN;
    __nv_bfloat16* Yb = g_vb + (size_t)b * CC * NN;

    float acc[8][8];
#pragma unroll
    for (int u = 0; u < 8; u++)
#pragma unroll
        for (int v = 0; v < 8; v++) acc[u][v] = 0.f;

    for (int k0 = 0; k0 < CC; k0 += 16) {
        {
            int m  = tid >> 1;
            int kk = (tid & 1) * 8;
            const float* p = W + (size_t)(m0 + m) * CC + k0 + kk;
            float4 v0 = *(const float4*)p;
            float4 v1 = *(const float4*)(p + 4);
            As[kk + 0][m] = v0.x; As[kk + 1][m] = v0.y;
            As[kk + 2][m] = v0.z; As[kk + 3][m] = v0.w;
            As[kk + 4][m] = v1.x; As[kk + 5][m] = v1.y;
            As[kk + 6][m] = v1.z; As[kk + 7][m] = v1.w;
        }
        {
            int kk = tid >> 4;
            int nn = (tid & 15) * 8;
            const float* p = xb + (size_t)(k0 + kk) * NN + n0 + nn;
            *(float4*)&Bs[kk][nn]     = *(const float4*)p;
            *(float4*)&Bs[kk][nn + 4] = *(const float4*)(p + 4);
        }
        __syncthreads();
#pragma unroll
        for (int kk = 0; kk < 16; kk++) {
            float4 a0 = *(float4*)&As[kk][ty * 8];
            float4 a1 = *(float4*)&As[kk][ty * 8 + 4];
            float4 b0 = *(float4*)&Bs[kk][tx * 8];
            float4 b1 = *(float4*)&Bs[kk][tx * 8 + 4];
            float a[8] = {a0.x, a0.y, a0.z, a0.w, a1.x, a1.y, a1.z, a1.w};
            float bb[8] = {b0.x, b0.y, b0.z, b0.w, b1.x, b1.y, b1.z, b1.w};
#pragma unroll
            for (int u = 0; u < 8; u++)
#pragma unroll
                for (int v = 0; v < 8; v++)
                    acc[u][v] = fmaf(a[u], bb[v], acc[u][v]);
        }
        __syncthreads();
    }

#pragma unroll
    for (int u = 0; u < 8; u++) {
        int m = m0 + ty * 8 + u;
        float s = scale[m], bi = bias[m];
        __nv_bfloat16 row8[8];
#pragma unroll
        for (int v = 0; v < 8; v++) {
            float r = fmaf(acc[u][v], s, bi);
            row8[v] = __float2bfloat16(r > 0.f ? r : 0.f);
        }
        *(uint4*)&Yb[(size_t)m * NN + n0 + tx * 8] = *(uint4*)row8;
    }
}

// ---------------------------------------------------------------------------
// energy: E[i,j] = sum_c qT[i][c] * kT[j][c].  mma.sync bf16, K=128 (NK=2).
// ---------------------------------------------------------------------------
__global__ __launch_bounds__(256)
void energy_kernel()
{
    extern __shared__ __align__(1024) char smem[];
    const uint32_t sb = smem_u32(smem);
    const int tid = threadIdx.x;
    const int lane = tid & 31, wid = tid >> 5;
    const int wm = wid >> 2, wn = wid & 3;
    const int bz = blockIdx.z, i0 = blockIdx.x * 128, j0 = blockIdx.y * 128;

    const uint4* qa = (const uint4*)(g_qT + (size_t)bz * NN * NP);
    const uint4* ka = (const uint4*)(g_kT + (size_t)bz * NN * NP);

    float acc[4][4][4];
#pragma unroll
    for (int i = 0; i < 4; i++)
#pragma unroll
        for (int j = 0; j < 4; j++)
#pragma unroll
            for (int k = 0; k < 4; k++) acc[i][j][k] = 0.f;

    gemm128x128<2>(sb, qa, ka, NP / 8, NP / 8, i0, j0, acc);

    float* Eb = g_energy + (size_t)bz * NN * NN;
    const int g = lane >> 2, tg = lane & 3;
#pragma unroll
    for (int mt = 0; mt < 4; mt++) {
        int m = i0 + wm * 64 + mt * 16 + g;
#pragma unroll
        for (int nt = 0; nt < 4; nt++) {
            int n = j0 + wn * 32 + nt * 8 + tg * 2;
            *(float2*)&Eb[(size_t)m * NN + n]       = make_float2(acc[mt][nt][0], acc[mt][nt][1]);
            *(float2*)&Eb[(size_t)(m + 8) * NN + n] = make_float2(acc[mt][nt][2], acc[mt][nt][3]);
        }
    }
}

// ---------------------------------------------------------------------------
// softmax: rows of g_energy (fp32) -> g_attnb (bf16). 256-thread block / row.
// ---------------------------------------------------------------------------
__global__ __launch_bounds__(256)
void softmax_kernel()
{
    __shared__ float red[8];
    const size_t row = blockIdx.x;
    const float* p = g_energy + row * (size_t)NN;
    __nv_bfloat16* o = g_attnb + row * (size_t)NN;
    const int tid = threadIdx.x;
    const int lane = tid & 31;
    const int wid  = tid >> 5;

    float vals[16];
    float mx = -1e30f;
#pragma unroll
    for (int j = 0; j < 16; j++) {
        vals[j] = p[tid + j * 256];
        mx = fmaxf(mx, vals[j]);
    }
#pragma unroll
    for (int off = 16; off > 0; off >>= 1)
        mx = fmaxf(mx, __shfl_xor_sync(0xffffffffu, mx, off));
    if (lane == 0) red[wid] = mx;
    __syncthreads();
    if (tid == 0) {
        float m = red[0];
#pragma unroll
        for (int i = 1; i < 8; i++) m = fmaxf(m, red[i]);
        red[0] = m;
    }
    __syncthreads();
    mx = red[0];
    __syncthreads();

    float sum = 0.f;
#pragma unroll
    for (int j = 0; j < 16; j++) {
        vals[j] = __expf(vals[j] - mx);
        sum += vals[j];
    }
#pragma unroll
    for (int off = 16; off > 0; off >>= 1)
        sum += __shfl_xor_sync(0xffffffffu, sum, off);
    if (lane == 0) red[wid] = sum;
    __syncthreads();
    if (tid == 0) {
        float s = 0.f;
#pragma unroll
        for (int i = 0; i < 8; i++) s += red[i];
        red[0] = s;
    }
    __syncthreads();
    const float inv = 1.f / red[0];

#pragma unroll
    for (int j = 0; j < 16; j++)
        o[tid + j * 256] = __float2bfloat16(vals[j] * inv);
}

// ---------------------------------------------------------------------------
// out: O[c,i] = sum_j v[c,j]*attn[i,j].  mma.sync bf16, K=4096 (NK=64).
// Epilogue fused: out = gamma*O + x (fp32).
// ---------------------------------------------------------------------------
__global__ __launch_bounds__(256)
void out_kernel(const float* __restrict__ gamma, const float* __restrict__ x,
                float* __restrict__ out)
{
    extern __shared__ __align__(1024) char smem[];
    const uint32_t sb = smem_u32(smem);
    const int tid = threadIdx.x;
    const int lane = tid & 31, wid = tid >> 5;
    const int wm = wid >> 2, wn = wid & 3;
    const int bz = blockIdx.z, c0 = blockIdx.x * 128, i0 = blockIdx.y * 128;

    const uint4* va = (const uint4*)(g_vb    + (size_t)bz * CC * NN);   // 512 uint4/row
    const uint4* aa = (const uint4*)(g_attnb + (size_t)bz * NN * NN);   // 512 uint4/row

    float acc[4][4][4];
#pragma unroll
    for (int i = 0; i < 4; i++)
#pragma unroll
        for (int j = 0; j < 4; j++)
#pragma unroll
            for (int k = 0; k < 4; k++) acc[i][j][k] = 0.f;

    gemm128x128<64>(sb, va, aa, NN / 8, NN / 8, c0, i0, acc);

    const int g = lane >> 2, tg = lane & 3;
#pragma unroll
    for (int mt = 0; mt < 4; mt++) {
#pragma unroll
        for (int half = 0; half < 2; half++) {
            int c = c0 + wm * 64 + mt * 16 + g + half * 8;
#pragma unroll
            for (int nt = 0; nt < 4; nt++) {
                int n = i0 + wn * 32 + nt * 8 + tg * 2;
                size_t gi = (size_t)c * NN + n;
                size_t bi = (size_t)bz * CC * NN + gi;
                float2 gm = *(const float2*)&gamma[gi];
                float2 xx = *(const float2*)&x[bi];
                float2 o;
                o.x = fmaf(gm.x, acc[mt][nt][half * 2 + 0], xx.x);
                o.y = fmaf(gm.y, acc[mt][nt][half * 2 + 1], xx.y);
                *(float2*)&out[bi] = o;
            }
        }
    }
}

// ---------------------------------------------------------------------------
extern "C" void kernel_launch(void* const* d_in, const int* in_sizes, int n_in,
                              void* d_out, int out_size)
{
    const float* x     = (const float*)d_in[0];
    const float* Wq    = (const float*)d_in[1];
    const float* Wk    = (const float*)d_in[2];
    const float* Wv    = (const float*)d_in[3];
    const float* sq    = (const float*)d_in[4];
    const float* bq    = (const float*)d_in[5];
    const float* sk    = (const float*)d_in[6];
    const float* bk    = (const float*)d_in[7];
    const float* sv    = (const float*)d_in[8];
    const float* bv    = (const float*)d_in[9];
    const float* gamma = (const float*)d_in[10];
    float* out = (float*)d_out;

    const int DSMEM = 65536;
    cudaFuncSetAttribute(energy_kernel, cudaFuncAttributeMaxDynamicSharedMemorySize, DSMEM);
    cudaFuncSetAttribute(out_kernel,    cudaFuncAttributeMaxDynamicSharedMemorySize, DSMEM);

    dim3 blk(256);

    proj_qk_kernel<<<dim3(NN / 128, BB), blk>>>(Wq, x, sq, bq, 0);
    proj_qk_kernel<<<dim3(NN / 128, BB), blk>>>(Wk, x, sk, bk, 1);
    proj_v_kernel<<<dim3(CC / 128, NN / 128, BB), blk>>>(Wv, x, sv, bv);

    energy_kernel<<<dim3(NN / 128, NN / 128, BB), blk, DSMEM>>>();

    softmax_kernel<<<BB * NN, blk>>>();

    out_kernel<<<dim3(CC / 128, NN / 128, BB), blk, DSMEM>>>(gamma, x, out);
}

// round 4
// speedup vs baseline: 6.0822x; 1.6278x over previous
#include <cuda_runtime.h>
#include <cuda_bf16.h>
#include <cstdint>

#define BB 8
#define CC 512
#define NN 4096
#define CQ 80
#define NP 128   // CQ padded to 128 for bf16 MMA K

// ---------------- scratch (device globals; allocation-guard safe) ----------
__device__ float          g_energy[(size_t)BB * NN * NN];   // 512 MB fp32
__device__ __nv_bfloat16  g_attnb [(size_t)BB * NN * NN];   // 256 MB bf16
__device__ __nv_bfloat16  g_vb    [(size_t)BB * CC * NN];   // 64 MB  [b][c][n]
__device__ __nv_bfloat16  g_qT    [(size_t)BB * NN * NP];   // 8 MB   [b][n][c] padded
__device__ __nv_bfloat16  g_kT    [(size_t)BB * NN * NP];   // 8 MB
__device__ __nv_bfloat16  g_xT    [(size_t)BB * NN * CC];   // 33.5 MB [b][n][c]
__device__ __nv_bfloat16  g_wv    [(size_t)CC * CC];        // Wv bf16 [512][512]
__device__ __nv_bfloat16  g_wqp   [(size_t)NP * CC];        // Wq padded [128][512]
__device__ __nv_bfloat16  g_wkp   [(size_t)NP * CC];        // Wk padded [128][512]

// ---------------- helpers ---------------------------------------------------
__device__ __forceinline__ uint32_t smem_u32(const void* p) {
    uint32_t a;
    asm("{ .reg .u64 t; cvta.to.shared.u64 t, %1; cvt.u32.u64 %0, t; }" : "=r"(a) : "l"(p));
    return a;
}
__device__ __forceinline__ void ldsm4(uint32_t& r0, uint32_t& r1, uint32_t& r2, uint32_t& r3,
                                      uint32_t addr) {
    asm volatile("ldmatrix.sync.aligned.m8n8.x4.shared.b16 {%0,%1,%2,%3}, [%4];"
                 : "=r"(r0), "=r"(r1), "=r"(r2), "=r"(r3) : "r"(addr));
}
__device__ __forceinline__ void mma16816(float* c, uint32_t a0, uint32_t a1, uint32_t a2,
                                         uint32_t a3, uint32_t b0, uint32_t b1) {
    asm volatile("mma.sync.aligned.m16n8k16.row.col.f32.bf16.bf16.f32 "
                 "{%0,%1,%2,%3},{%4,%5,%6,%7},{%8,%9},{%0,%1,%2,%3};"
                 : "+f"(c[0]), "+f"(c[1]), "+f"(c[2]), "+f"(c[3])
                 : "r"(a0), "r"(a1), "r"(a2), "r"(a3), "r"(b0), "r"(b1));
}
#define CP_ASYNC16(dst, src) \
    asm volatile("cp.async.cg.shared.global [%0], [%1], 16;" :: "r"(dst), "l"(src))
#define CP_COMMIT() asm volatile("cp.async.commit_group;" ::: "memory")
#define CP_WAIT1()  asm volatile("cp.async.wait_group 1;" ::: "memory")
#define CP_WAIT0()  asm volatile("cp.async.wait_group 0;" ::: "memory")

// smem tile: 128 rows x 64 bf16 (128B rows). chunk c in [0,8) of 16B; xor swizzle.
#define SW(r, c) ((uint32_t)(((r) * 128) + ((((c) ^ ((r) & 7))) * 16)))

// ---------------------------------------------------------------------------
// Shared 128x128 bf16 GEMM body.  C[128,128] += A[128,K] * B[128,K]^T
// A,B row-major k-contig (strides in uint4 units). BK=64, cp.async dbl buffer.
// 8 warps of 64x32, m16n8k16 fragments.
// ---------------------------------------------------------------------------
template <int NK>
__device__ __forceinline__ void gemm128x128(uint32_t sb, const uint4* __restrict__ Ag,
                                            const uint4* __restrict__ Bg, int aStride,
                                            int bStride, int m0, int n0,
                                            float (&acc)[4][4][4]) {
    const int tid = threadIdx.x;
    const int lane = tid & 31, wid = tid >> 5;
    const int wm = wid >> 2, wn = wid & 3;
    const int lr = tid >> 3, lc = tid & 7;

    int a_r[4], b_r[2];
#pragma unroll
    for (int mt = 0; mt < 4; mt++) a_r[mt] = wm * 64 + mt * 16 + ((lane >> 3) & 1) * 8 + (lane & 7);
#pragma unroll
    for (int p = 0; p < 2; p++) b_r[p] = wn * 32 + p * 16 + ((lane >> 4) & 1) * 8 + (lane & 7);
    const int a_kc = (lane >> 4) & 1;
    const int b_kc = (lane >> 3) & 1;

    {
        uint32_t dA = sb, dB = sb + 16384;
#pragma unroll
        for (int p = 0; p < 4; p++) {
            int r = p * 32 + lr;
            CP_ASYNC16(dA + SW(r, lc), (const void*)(Ag + (size_t)(m0 + r) * aStride + lc));
            CP_ASYNC16(dB + SW(r, lc), (const void*)(Bg + (size_t)(n0 + r) * bStride + lc));
        }
        CP_COMMIT();
    }

#pragma unroll 1
    for (int t = 0; t < NK; t++) {
        if (t + 1 < NK) {
            uint32_t dA = sb + ((t + 1) & 1) * 32768, dB = dA + 16384;
#pragma unroll
            for (int p = 0; p < 4; p++) {
                int r = p * 32 + lr;
                CP_ASYNC16(dA + SW(r, lc),
                           (const void*)(Ag + (size_t)(m0 + r) * aStride + (t + 1) * 8 + lc));
                CP_ASYNC16(dB + SW(r, lc),
                           (const void*)(Bg + (size_t)(n0 + r) * bStride + (t + 1) * 8 + lc));
            }
            CP_COMMIT();
            CP_WAIT1();
        } else {
            CP_WAIT0();
        }
        __syncthreads();

        const uint32_t Asb = sb + (t & 1) * 32768;
        const uint32_t Bsb = Asb + 16384;
#pragma unroll
        for (int ks = 0; ks < 4; ks++) {
            uint32_t aF[4][4], bF[2][4];
#pragma unroll
            for (int mt = 0; mt < 4; mt++)
                ldsm4(aF[mt][0], aF[mt][1], aF[mt][2], aF[mt][3],
                      Asb + SW(a_r[mt], ks * 2 + a_kc));
#pragma unroll
            for (int p = 0; p < 2; p++)
                ldsm4(bF[p][0], bF[p][1], bF[p][2], bF[p][3],
                      Bsb + SW(b_r[p], ks * 2 + b_kc));
#pragma unroll
            for (int mt = 0; mt < 4; mt++) {
                mma16816(acc[mt][0], aF[mt][0], aF[mt][1], aF[mt][2], aF[mt][3], bF[0][0], bF[0][1]);
                mma16816(acc[mt][1], aF[mt][0], aF[mt][1], aF[mt][2], aF[mt][3], bF[0][2], bF[0][3]);
                mma16816(acc[mt][2], aF[mt][0], aF[mt][1], aF[mt][2], aF[mt][3], bF[1][0], bF[1][1]);
                mma16816(acc[mt][3], aF[mt][0], aF[mt][1], aF[mt][2], aF[mt][3], bF[1][2], bF[1][3]);
            }
        }
        __syncthreads();
    }
}

// ---------------------------------------------------------------------------
// convert_w: Wv -> bf16; Wq/Wk -> bf16 zero-padded [128][512].
// ---------------------------------------------------------------------------
__global__ __launch_bounds__(256)
void convert_w_kernel(const float* __restrict__ Wv, const float* __restrict__ Wq,
                      const float* __restrict__ Wk)
{
    int idx = blockIdx.x * 256 + threadIdx.x;
    if (idx < CC * CC) {
        g_wv[idx] = __float2bfloat16(Wv[idx]);
    } else if (idx < CC * CC + NP * CC) {
        int i = idx - CC * CC;
        int row = i >> 9, col = i & 511;
        g_wqp[i] = __float2bfloat16(row < CQ ? Wq[row * CC + col] : 0.f);
    } else {
        int i = idx - CC * CC - NP * CC;
        int row = i >> 9, col = i & 511;
        g_wkp[i] = __float2bfloat16(row < CQ ? Wk[row * CC + col] : 0.f);
    }
}

// ---------------------------------------------------------------------------
// transpose_x: x [b][c][n] fp32 -> xT [b][n][c] bf16. 128x128 tiles.
// grid (CC/128, NN/128, BB), 256 threads.
// ---------------------------------------------------------------------------
__global__ __launch_bounds__(256)
void transpose_x_kernel(const float* __restrict__ x)
{
    __shared__ __nv_bfloat16 st[128][136];
    const int b  = blockIdx.z;
    const int c0 = blockIdx.x * 128;
    const int n0 = blockIdx.y * 128;
    const int tid = threadIdx.x;

    const float* xb = x + (size_t)b * CC * NN;
#pragma unroll
    for (int k = 0; k < 8; k++) {
        int row = k * 16 + (tid >> 4);       // c offset
        int col = (tid & 15) * 8;            // n offset
        const float* p = xb + (size_t)(c0 + row) * NN + n0 + col;
        float4 v0 = *(const float4*)p;
        float4 v1 = *(const float4*)(p + 4);
        st[col + 0][row] = __float2bfloat16(v0.x);
        st[col + 1][row] = __float2bfloat16(v0.y);
        st[col + 2][row] = __float2bfloat16(v0.z);
        st[col + 3][row] = __float2bfloat16(v0.w);
        st[col + 4][row] = __float2bfloat16(v1.x);
        st[col + 5][row] = __float2bfloat16(v1.y);
        st[col + 6][row] = __float2bfloat16(v1.z);
        st[col + 7][row] = __float2bfloat16(v1.w);
    }
    __syncthreads();

    uint4* xT = (uint4*)(g_xT + (size_t)b * NN * CC);
#pragma unroll
    for (int k = 0; k < 8; k++) {
        int idx = k * 256 + tid;
        int r = idx >> 4, j = idx & 15;      // r: n offset, j: c chunk of 8
        uint4 val = *(uint4*)&st[r][j * 8];
        xT[(size_t)(n0 + r) * (CC / 8) + (c0 >> 3) + j] = val;
    }
}

// ---------------------------------------------------------------------------
// proj_qk: qT[n][c] = relu(scale[c]*(xT[n,:]·Wq[c,:]) + bias[c]), c<80 else 0.
// Tensor-core GEMM, K=512. grid (NN/128, 1, BB).
// ---------------------------------------------------------------------------
__global__ __launch_bounds__(256)
void proj_qk_kernel(const float* __restrict__ scale, const float* __restrict__ bias,
                    int which)
{
    extern __shared__ __align__(1024) char smem[];
    const uint32_t sb = smem_u32(smem);
    const int tid = threadIdx.x;
    const int lane = tid & 31, wid = tid >> 5;
    const int wm = wid >> 2, wn = wid & 3;
    const int bz = blockIdx.z, n0 = blockIdx.x * 128;

    const uint4* Ag = (const uint4*)(g_xT + (size_t)bz * NN * CC);
    const uint4* Bg = (const uint4*)(which ? g_wkp : g_wqp);

    float acc[4][4][4];
#pragma unroll
    for (int i = 0; i < 4; i++)
#pragma unroll
        for (int j = 0; j < 4; j++)
#pragma unroll
            for (int k = 0; k < 4; k++) acc[i][j][k] = 0.f;

    gemm128x128<8>(sb, Ag, Bg, CC / 8, CC / 8, n0, 0, acc);

    __nv_bfloat16* qT = (which ? g_kT : g_qT) + (size_t)bz * NN * NP;
    const int g = lane >> 2, tg = lane & 3;
#pragma unroll
    for (int mt = 0; mt < 4; mt++) {
#pragma unroll
        for (int half = 0; half < 2; half++) {
            int row = n0 + wm * 64 + mt * 16 + g + half * 8;
#pragma unroll
            for (int nt = 0; nt < 4; nt++) {
                int c = wn * 32 + nt * 8 + tg * 2;
                float r0 = 0.f, r1 = 0.f;
                if (c < CQ) {
                    r0 = fmaf(acc[mt][nt][half * 2 + 0], scale[c], bias[c]);
                    r1 = fmaf(acc[mt][nt][half * 2 + 1], scale[c + 1], bias[c + 1]);
                    r0 = r0 > 0.f ? r0 : 0.f;
                    r1 = r1 > 0.f ? r1 : 0.f;
                }
                __nv_bfloat162 pk;
                pk.x = __float2bfloat16(r0);
                pk.y = __float2bfloat16(r1);
                *(__nv_bfloat162*)&qT[(size_t)row * NP + c] = pk;
            }
        }
    }
}

// ---------------------------------------------------------------------------
// proj_v: v[c][n] = relu(scale[c]*(Wv[c,:]·xT[n,:]) + bias[c]). K=512.
// grid (CC/128, NN/128, BB).
// ---------------------------------------------------------------------------
__global__ __launch_bounds__(256)
void proj_v_kernel(const float* __restrict__ scale, const float* __restrict__ bias)
{
    extern __shared__ __align__(1024) char smem[];
    const uint32_t sb = smem_u32(smem);
    const int tid = threadIdx.x;
    const int lane = tid & 31, wid = tid >> 5;
    const int wm = wid >> 2, wn = wid & 3;
    const int bz = blockIdx.z, c0 = blockIdx.x * 128, n0 = blockIdx.y * 128;

    const uint4* Ag = (const uint4*)g_wv;
    const uint4* Bg = (const uint4*)(g_xT + (size_t)bz * NN * CC);

    float acc[4][4][4];
#pragma unroll
    for (int i = 0; i < 4; i++)
#pragma unroll
        for (int j = 0; j < 4; j++)
#pragma unroll
            for (int k = 0; k < 4; k++) acc[i][j][k] = 0.f;

    gemm128x128<8>(sb, Ag, Bg, CC / 8, CC / 8, c0, n0, acc);

    __nv_bfloat16* Yb = g_vb + (size_t)bz * CC * NN;
    const int g = lane >> 2, tg = lane & 3;
#pragma unroll
    for (int mt = 0; mt < 4; mt++) {
#pragma unroll
        for (int half = 0; half < 2; half++) {
            int c = c0 + wm * 64 + mt * 16 + g + half * 8;
            float s = scale[c], bi = bias[c];
#pragma unroll
            for (int nt = 0; nt < 4; nt++) {
                int n = n0 + wn * 32 + nt * 8 + tg * 2;
                float r0 = fmaf(acc[mt][nt][half * 2 + 0], s, bi);
                float r1 = fmaf(acc[mt][nt][half * 2 + 1], s, bi);
                __nv_bfloat162 pk;
                pk.x = __float2bfloat16(r0 > 0.f ? r0 : 0.f);
                pk.y = __float2bfloat16(r1 > 0.f ? r1 : 0.f);
                *(__nv_bfloat162*)&Yb[(size_t)c * NN + n] = pk;
            }
        }
    }
}

// ---------------------------------------------------------------------------
// energy: E[i,j] = sum_c qT[i][c] * kT[j][c].  K=128 (NK=2).
// ---------------------------------------------------------------------------
__global__ __launch_bounds__(256)
void energy_kernel()
{
    extern __shared__ __align__(1024) char smem[];
    const uint32_t sb = smem_u32(smem);
    const int tid = threadIdx.x;
    const int lane = tid & 31, wid = tid >> 5;
    const int wm = wid >> 2, wn = wid & 3;
    const int bz = blockIdx.z, i0 = blockIdx.x * 128, j0 = blockIdx.y * 128;

    const uint4* qa = (const uint4*)(g_qT + (size_t)bz * NN * NP);
    const uint4* ka = (const uint4*)(g_kT + (size_t)bz * NN * NP);

    float acc[4][4][4];
#pragma unroll
    for (int i = 0; i < 4; i++)
#pragma unroll
        for (int j = 0; j < 4; j++)
#pragma unroll
            for (int k = 0; k < 4; k++) acc[i][j][k] = 0.f;

    gemm128x128<2>(sb, qa, ka, NP / 8, NP / 8, i0, j0, acc);

    float* Eb = g_energy + (size_t)bz * NN * NN;
    const int g = lane >> 2, tg = lane & 3;
#pragma unroll
    for (int mt = 0; mt < 4; mt++) {
        int m = i0 + wm * 64 + mt * 16 + g;
#pragma unroll
        for (int nt = 0; nt < 4; nt++) {
            int n = j0 + wn * 32 + nt * 8 + tg * 2;
            *(float2*)&Eb[(size_t)m * NN + n]       = make_float2(acc[mt][nt][0], acc[mt][nt][1]);
            *(float2*)&Eb[(size_t)(m + 8) * NN + n] = make_float2(acc[mt][nt][2], acc[mt][nt][3]);
        }
    }
}

// ---------------------------------------------------------------------------
// softmax: rows of g_energy (fp32) -> g_attnb (bf16). 256-thread block / row.
// ---------------------------------------------------------------------------
__global__ __launch_bounds__(256)
void softmax_kernel()
{
    __shared__ float red[8];
    const size_t row = blockIdx.x;
    const float* p = g_energy + row * (size_t)NN;
    __nv_bfloat16* o = g_attnb + row * (size_t)NN;
    const int tid = threadIdx.x;
    const int lane = tid & 31;
    const int wid  = tid >> 5;

    float vals[16];
    float mx = -1e30f;
#pragma unroll
    for (int j = 0; j < 16; j++) {
        vals[j] = p[tid + j * 256];
        mx = fmaxf(mx, vals[j]);
    }
#pragma unroll
    for (int off = 16; off > 0; off >>= 1)
        mx = fmaxf(mx, __shfl_xor_sync(0xffffffffu, mx, off));
    if (lane == 0) red[wid] = mx;
    __syncthreads();
    if (tid == 0) {
        float m = red[0];
#pragma unroll
        for (int i = 1; i < 8; i++) m = fmaxf(m, red[i]);
        red[0] = m;
    }
    __syncthreads();
    mx = red[0];
    __syncthreads();

    float sum = 0.f;
#pragma unroll
    for (int j = 0; j < 16; j++) {
        vals[j] = __expf(vals[j] - mx);
        sum += vals[j];
    }
#pragma unroll
    for (int off = 16; off > 0; off >>= 1)
        sum += __shfl_xor_sync(0xffffffffu, sum, off);
    if (lane == 0) red[wid] = sum;
    __syncthreads();
    if (tid == 0) {
        float s = 0.f;
#pragma unroll
        for (int i = 0; i < 8; i++) s += red[i];
        red[0] = s;
    }
    __syncthreads();
    const float inv = 1.f / red[0];

#pragma unroll
    for (int j = 0; j < 16; j++)
        o[tid + j * 256] = __float2bfloat16(vals[j] * inv);
}

// ---------------------------------------------------------------------------
// out: O[c,i] = sum_j v[c,j]*attn[i,j].  K=4096 (NK=64). Fused gamma*O + x.
// ---------------------------------------------------------------------------
__global__ __launch_bounds__(256)
void out_kernel(const float* __restrict__ gamma, const float* __restrict__ x,
                float* __restrict__ out)
{
    extern __shared__ __align__(1024) char smem[];
    const uint32_t sb = smem_u32(smem);
    const int tid = threadIdx.x;
    const int lane = tid & 31, wid = tid >> 5;
    const int wm = wid >> 2, wn = wid & 3;
    const int bz = blockIdx.z, c0 = blockIdx.x * 128, i0 = blockIdx.y * 128;

    const uint4* va = (const uint4*)(g_vb    + (size_t)bz * CC * NN);
    const uint4* aa = (const uint4*)(g_attnb + (size_t)bz * NN * NN);

    float acc[4][4][4];
#pragma unroll
    for (int i = 0; i < 4; i++)
#pragma unroll
        for (int j = 0; j < 4; j++)
#pragma unroll
            for (int k = 0; k < 4; k++) acc[i][j][k] = 0.f;

    gemm128x128<64>(sb, va, aa, NN / 8, NN / 8, c0, i0, acc);

    const int g = lane >> 2, tg = lane & 3;
#pragma unroll
    for (int mt = 0; mt < 4; mt++) {
#pragma unroll
        for (int half = 0; half < 2; half++) {
            int c = c0 + wm * 64 + mt * 16 + g + half * 8;
#pragma unroll
            for (int nt = 0; nt < 4; nt++) {
                int n = i0 + wn * 32 + nt * 8 + tg * 2;
                size_t gi = (size_t)c * NN + n;
                size_t bi = (size_t)bz * CC * NN + gi;
                float2 gm = *(const float2*)&gamma[gi];
                float2 xx = *(const float2*)&x[bi];
                float2 o;
                o.x = fmaf(gm.x, acc[mt][nt][half * 2 + 0], xx.x);
                o.y = fmaf(gm.y, acc[mt][nt][half * 2 + 1], xx.y);
                *(float2*)&out[bi] = o;
            }
        }
    }
}

// ---------------------------------------------------------------------------
extern "C" void kernel_launch(void* const* d_in, const int* in_sizes, int n_in,
                              void* d_out, int out_size)
{
    const float* x     = (const float*)d_in[0];
    const float* Wq    = (const float*)d_in[1];
    const float* Wk    = (const float*)d_in[2];
    const float* Wv    = (const float*)d_in[3];
    const float* sq    = (const float*)d_in[4];
    const float* bq    = (const float*)d_in[5];
    const float* sk    = (const float*)d_in[6];
    const float* bk    = (const float*)d_in[7];
    const float* sv    = (const float*)d_in[8];
    const float* bv    = (const float*)d_in[9];
    const float* gamma = (const float*)d_in[10];
    float* out = (float*)d_out;

    const int DSMEM = 65536;
    cudaFuncSetAttribute(proj_qk_kernel, cudaFuncAttributeMaxDynamicSharedMemorySize, DSMEM);
    cudaFuncSetAttribute(proj_v_kernel,  cudaFuncAttributeMaxDynamicSharedMemorySize, DSMEM);
    cudaFuncSetAttribute(energy_kernel,  cudaFuncAttributeMaxDynamicSharedMemorySize, DSMEM);
    cudaFuncSetAttribute(out_kernel,     cudaFuncAttributeMaxDynamicSharedMemorySize, DSMEM);

    dim3 blk(256);

    // Prep: weights to bf16 (padded), x transposed to bf16 [b][n][c]
    convert_w_kernel<<<(CC * CC + 2 * NP * CC) / 256, blk>>>(Wv, Wq, Wk);
    transpose_x_kernel<<<dim3(CC / 128, NN / 128, BB), blk>>>(x);

    // Projections (tensor core)
    proj_qk_kernel<<<dim3(NN / 128, 1, BB), blk, DSMEM>>>(sq, bq, 0);
    proj_qk_kernel<<<dim3(NN / 128, 1, BB), blk, DSMEM>>>(sk, bk, 1);
    proj_v_kernel<<<dim3(CC / 128, NN / 128, BB), blk, DSMEM>>>(sv, bv);

    // Attention
    energy_kernel<<<dim3(NN / 128, NN / 128, BB), blk, DSMEM>>>();
    softmax_kernel<<<BB * NN, blk>>>();
    out_kernel<<<dim3(CC / 128, NN / 128, BB), blk, DSMEM>>>(gamma, x, out);
}

// round 5
// speedup vs baseline: 6.2410x; 1.0261x over previous
#include <cuda_runtime.h>
#include <cuda_bf16.h>
#include <cstdint>

#define BB 8
#define CC 512
#define NN 4096
#define CQ 80
#define NP 128   // CQ padded to 128 for bf16 MMA K

// ---------------- scratch (device globals; allocation-guard safe) ----------
__device__ __nv_bfloat16  g_attnb [(size_t)BB * NN * NN];   // 256 MB bf16 (unnormalized P)
__device__ float          g_linv  [(size_t)BB * NN];        // 1/rowsum
__device__ __nv_bfloat16  g_vb    [(size_t)BB * CC * NN];   // 64 MB  [b][c][n]
__device__ __nv_bfloat16  g_qT    [(size_t)BB * NN * NP];   // 8 MB   [b][n][c] padded
__device__ __nv_bfloat16  g_kT    [(size_t)BB * NN * NP];   // 8 MB
__device__ __nv_bfloat16  g_xT    [(size_t)BB * NN * CC];   // 33.5 MB [b][n][c]
__device__ __nv_bfloat16  g_wv    [(size_t)CC * CC];        // Wv bf16
__device__ __nv_bfloat16  g_wqp   [(size_t)NP * CC];        // Wq padded [128][512]
__device__ __nv_bfloat16  g_wkp   [(size_t)NP * CC];        // Wk padded [128][512]

// ---------------- helpers ---------------------------------------------------
__device__ __forceinline__ uint32_t smem_u32(const void* p) {
    uint32_t a;
    asm("{ .reg .u64 t; cvta.to.shared.u64 t, %1; cvt.u32.u64 %0, t; }" : "=r"(a) : "l"(p));
    return a;
}
__device__ __forceinline__ void ldsm4(uint32_t& r0, uint32_t& r1, uint32_t& r2, uint32_t& r3,
                                      uint32_t addr) {
    asm volatile("ldmatrix.sync.aligned.m8n8.x4.shared.b16 {%0,%1,%2,%3}, [%4];"
                 : "=r"(r0), "=r"(r1), "=r"(r2), "=r"(r3) : "r"(addr));
}
__device__ __forceinline__ void mma16816(float* c, uint32_t a0, uint32_t a1, uint32_t a2,
                                         uint32_t a3, uint32_t b0, uint32_t b1) {
    asm volatile("mma.sync.aligned.m16n8k16.row.col.f32.bf16.bf16.f32 "
                 "{%0,%1,%2,%3},{%4,%5,%6,%7},{%8,%9},{%0,%1,%2,%3};"
                 : "+f"(c[0]), "+f"(c[1]), "+f"(c[2]), "+f"(c[3])
                 : "r"(a0), "r"(a1), "r"(a2), "r"(a3), "r"(b0), "r"(b1));
}
#define CP_ASYNC16(dst, src) \
    asm volatile("cp.async.cg.shared.global [%0], [%1], 16;" :: "r"(dst), "l"(src))
#define CP_COMMIT() asm volatile("cp.async.commit_group;" ::: "memory")
#define CP_WAIT1()  asm volatile("cp.async.wait_group 1;" ::: "memory")
#define CP_WAIT0()  asm volatile("cp.async.wait_group 0;" ::: "memory")

// 64-bf16 (128B) rows swizzle (gemm128x128 tiles)
#define SW(r, c) ((uint32_t)(((r) * 128) + ((((c) ^ ((r) & 7))) * 16)))
// 128-bf16 (256B) rows swizzle (fused kernel tiles), chunk in [0,16)
#define SW2(r, c) ((uint32_t)(((r) * 256) + ((((c) ^ ((r) & 7))) * 16)))

// ---------------------------------------------------------------------------
// Shared 128x128 bf16 GEMM body.  C[128,128] += A[128,K] * B[128,K]^T
// ---------------------------------------------------------------------------
template <int NK>
__device__ __forceinline__ void gemm128x128(uint32_t sb, const uint4* __restrict__ Ag,
                                            const uint4* __restrict__ Bg, int aStride,
                                            int bStride, int m0, int n0,
                                            float (&acc)[4][4][4]) {
    const int tid = threadIdx.x;
    const int lane = tid & 31, wid = tid >> 5;
    const int wm = wid >> 2, wn = wid & 3;
    const int lr = tid >> 3, lc = tid & 7;

    int a_r[4], b_r[2];
#pragma unroll
    for (int mt = 0; mt < 4; mt++) a_r[mt] = wm * 64 + mt * 16 + ((lane >> 3) & 1) * 8 + (lane & 7);
#pragma unroll
    for (int p = 0; p < 2; p++) b_r[p] = wn * 32 + p * 16 + ((lane >> 4) & 1) * 8 + (lane & 7);
    const int a_kc = (lane >> 4) & 1;
    const int b_kc = (lane >> 3) & 1;

    {
        uint32_t dA = sb, dB = sb + 16384;
#pragma unroll
        for (int p = 0; p < 4; p++) {
            int r = p * 32 + lr;
            CP_ASYNC16(dA + SW(r, lc), (const void*)(Ag + (size_t)(m0 + r) * aStride + lc));
            CP_ASYNC16(dB + SW(r, lc), (const void*)(Bg + (size_t)(n0 + r) * bStride + lc));
        }
        CP_COMMIT();
    }

#pragma unroll 1
    for (int t = 0; t < NK; t++) {
        if (t + 1 < NK) {
            uint32_t dA = sb + ((t + 1) & 1) * 32768, dB = dA + 16384;
#pragma unroll
            for (int p = 0; p < 4; p++) {
                int r = p * 32 + lr;
                CP_ASYNC16(dA + SW(r, lc),
                           (const void*)(Ag + (size_t)(m0 + r) * aStride + (t + 1) * 8 + lc));
                CP_ASYNC16(dB + SW(r, lc),
                           (const void*)(Bg + (size_t)(n0 + r) * bStride + (t + 1) * 8 + lc));
            }
            CP_COMMIT();
            CP_WAIT1();
        } else {
            CP_WAIT0();
        }
        __syncthreads();

        const uint32_t Asb = sb + (t & 1) * 32768;
        const uint32_t Bsb = Asb + 16384;
#pragma unroll
        for (int ks = 0; ks < 4; ks++) {
            uint32_t aF[4][4], bF[2][4];
#pragma unroll
            for (int mt = 0; mt < 4; mt++)
                ldsm4(aF[mt][0], aF[mt][1], aF[mt][2], aF[mt][3],
                      Asb + SW(a_r[mt], ks * 2 + a_kc));
#pragma unroll
            for (int p = 0; p < 2; p++)
                ldsm4(bF[p][0], bF[p][1], bF[p][2], bF[p][3],
                      Bsb + SW(b_r[p], ks * 2 + b_kc));
#pragma unroll
            for (int mt = 0; mt < 4; mt++) {
                mma16816(acc[mt][0], aF[mt][0], aF[mt][1], aF[mt][2], aF[mt][3], bF[0][0], bF[0][1]);
                mma16816(acc[mt][1], aF[mt][0], aF[mt][1], aF[mt][2], aF[mt][3], bF[0][2], bF[0][3]);
                mma16816(acc[mt][2], aF[mt][0], aF[mt][1], aF[mt][2], aF[mt][3], bF[1][0], bF[1][1]);
                mma16816(acc[mt][3], aF[mt][0], aF[mt][1], aF[mt][2], aF[mt][3], bF[1][2], bF[1][3]);
            }
        }
        __syncthreads();
    }
}

// ---------------------------------------------------------------------------
// convert_w
// ---------------------------------------------------------------------------
__global__ __launch_bounds__(256)
void convert_w_kernel(const float* __restrict__ Wv, const float* __restrict__ Wq,
                      const float* __restrict__ Wk)
{
    int idx = blockIdx.x * 256 + threadIdx.x;
    if (idx < CC * CC) {
        g_wv[idx] = __float2bfloat16(Wv[idx]);
    } else if (idx < CC * CC + NP * CC) {
        int i = idx - CC * CC;
        int row = i >> 9, col = i & 511;
        g_wqp[i] = __float2bfloat16(row < CQ ? Wq[row * CC + col] : 0.f);
    } else {
        int i = idx - CC * CC - NP * CC;
        int row = i >> 9, col = i & 511;
        g_wkp[i] = __float2bfloat16(row < CQ ? Wk[row * CC + col] : 0.f);
    }
}

// ---------------------------------------------------------------------------
// transpose_x: x [b][c][n] fp32 -> xT [b][n][c] bf16.
// ---------------------------------------------------------------------------
__global__ __launch_bounds__(256)
void transpose_x_kernel(const float* __restrict__ x)
{
    __shared__ __nv_bfloat16 st[128][136];
    const int b  = blockIdx.z;
    const int c0 = blockIdx.x * 128;
    const int n0 = blockIdx.y * 128;
    const int tid = threadIdx.x;

    const float* xb = x + (size_t)b * CC * NN;
#pragma unroll
    for (int k = 0; k < 8; k++) {
        int row = k * 16 + (tid >> 4);
        int col = (tid & 15) * 8;
        const float* p = xb + (size_t)(c0 + row) * NN + n0 + col;
        float4 v0 = *(const float4*)p;
        float4 v1 = *(const float4*)(p + 4);
        st[col + 0][row] = __float2bfloat16(v0.x);
        st[col + 1][row] = __float2bfloat16(v0.y);
        st[col + 2][row] = __float2bfloat16(v0.z);
        st[col + 3][row] = __float2bfloat16(v0.w);
        st[col + 4][row] = __float2bfloat16(v1.x);
        st[col + 5][row] = __float2bfloat16(v1.y);
        st[col + 6][row] = __float2bfloat16(v1.z);
        st[col + 7][row] = __float2bfloat16(v1.w);
    }
    __syncthreads();

    uint4* xT = (uint4*)(g_xT + (size_t)b * NN * CC);
#pragma unroll
    for (int k = 0; k < 8; k++) {
        int idx = k * 256 + tid;
        int r = idx >> 4, j = idx & 15;
        uint4 val = *(uint4*)&st[r][j * 8];
        xT[(size_t)(n0 + r) * (CC / 8) + (c0 >> 3) + j] = val;
    }
}

// ---------------------------------------------------------------------------
// proj_qk / proj_v (unchanged from R4)
// ---------------------------------------------------------------------------
__global__ __launch_bounds__(256)
void proj_qk_kernel(const float* __restrict__ scale, const float* __restrict__ bias,
                    int which)
{
    extern __shared__ __align__(1024) char smem[];
    const uint32_t sb = smem_u32(smem);
    const int tid = threadIdx.x;
    const int lane = tid & 31, wid = tid >> 5;
    const int wm = wid >> 2, wn = wid & 3;
    const int bz = blockIdx.z, n0 = blockIdx.x * 128;

    const uint4* Ag = (const uint4*)(g_xT + (size_t)bz * NN * CC);
    const uint4* Bg = (const uint4*)(which ? g_wkp : g_wqp);

    float acc[4][4][4];
#pragma unroll
    for (int i = 0; i < 4; i++)
#pragma unroll
        for (int j = 0; j < 4; j++)
#pragma unroll
            for (int k = 0; k < 4; k++) acc[i][j][k] = 0.f;

    gemm128x128<8>(sb, Ag, Bg, CC / 8, CC / 8, n0, 0, acc);

    __nv_bfloat16* qT = (which ? g_kT : g_qT) + (size_t)bz * NN * NP;
    const int g = lane >> 2, tg = lane & 3;
#pragma unroll
    for (int mt = 0; mt < 4; mt++) {
#pragma unroll
        for (int half = 0; half < 2; half++) {
            int row = n0 + wm * 64 + mt * 16 + g + half * 8;
#pragma unroll
            for (int nt = 0; nt < 4; nt++) {
                int c = wn * 32 + nt * 8 + tg * 2;
                float r0 = 0.f, r1 = 0.f;
                if (c < CQ) {
                    r0 = fmaf(acc[mt][nt][half * 2 + 0], scale[c], bias[c]);
                    r1 = fmaf(acc[mt][nt][half * 2 + 1], scale[c + 1], bias[c + 1]);
                    r0 = r0 > 0.f ? r0 : 0.f;
                    r1 = r1 > 0.f ? r1 : 0.f;
                }
                __nv_bfloat162 pk;
                pk.x = __float2bfloat16(r0);
                pk.y = __float2bfloat16(r1);
                *(__nv_bfloat162*)&qT[(size_t)row * NP + c] = pk;
            }
        }
    }
}

__global__ __launch_bounds__(256)
void proj_v_kernel(const float* __restrict__ scale, const float* __restrict__ bias)
{
    extern __shared__ __align__(1024) char smem[];
    const uint32_t sb = smem_u32(smem);
    const int tid = threadIdx.x;
    const int lane = tid & 31, wid = tid >> 5;
    const int wm = wid >> 2, wn = wid & 3;
    const int bz = blockIdx.z, c0 = blockIdx.x * 128, n0 = blockIdx.y * 128;

    const uint4* Ag = (const uint4*)g_wv;
    const uint4* Bg = (const uint4*)(g_xT + (size_t)bz * NN * CC);

    float acc[4][4][4];
#pragma unroll
    for (int i = 0; i < 4; i++)
#pragma unroll
        for (int j = 0; j < 4; j++)
#pragma unroll
            for (int k = 0; k < 4; k++) acc[i][j][k] = 0.f;

    gemm128x128<8>(sb, Ag, Bg, CC / 8, CC / 8, c0, n0, acc);

    __nv_bfloat16* Yb = g_vb + (size_t)bz * CC * NN;
    const int g = lane >> 2, tg = lane & 3;
#pragma unroll
    for (int mt = 0; mt < 4; mt++) {
#pragma unroll
        for (int half = 0; half < 2; half++) {
            int c = c0 + wm * 64 + mt * 16 + g + half * 8;
            float s = scale[c], bi = bias[c];
#pragma unroll
            for (int nt = 0; nt < 4; nt++) {
                int n = n0 + wn * 32 + nt * 8 + tg * 2;
                float r0 = fmaf(acc[mt][nt][half * 2 + 0], s, bi);
                float r1 = fmaf(acc[mt][nt][half * 2 + 1], s, bi);
                __nv_bfloat162 pk;
                pk.x = __float2bfloat16(r0 > 0.f ? r0 : 0.f);
                pk.y = __float2bfloat16(r1 > 0.f ? r1 : 0.f);
                *(__nv_bfloat162*)&Yb[(size_t)c * NN + n] = pk;
            }
        }
    }
}

// ---------------------------------------------------------------------------
// FUSED energy+softmax: per CTA (i-tile of 64 rows, batch b):
//   pass 1 (tt 0..31):  E = q_i · k_j^T, track running row max (registers)
//   pass 2 (tt 32..63): recompute E, P = exp(E - m) -> bf16 g_attnb, row sums
//   writes g_linv = 1/rowsum.
// smem: q 16KB | k dbl 2x32KB | P 16KB | red 1KB | m 256B   (~97.5 KB)
// ---------------------------------------------------------------------------
#define FQ_OFF 0
#define FK_OFF 16384
#define FP_OFF 81920
#define FRED_OFF 98304
#define FM_OFF 99328
#define FSMEM 99584

__global__ __launch_bounds__(256)
void energy_softmax_kernel()
{
    extern __shared__ __align__(1024) char smem[];
    const uint32_t sb = smem_u32(smem);
    const int tid = threadIdx.x;
    const int lane = tid & 31, wid = tid >> 5;
    const int wm = wid >> 2, wn = wid & 3;           // wm 0..1, wn 0..3
    const int g = lane >> 2, tg = lane & 3;
    const int bz = blockIdx.y, i0 = blockIdx.x * 64;

    const char* qg = (const char*)(g_qT + ((size_t)bz * NN + (size_t)i0) * NP);
    const char* kg = (const char*)(g_kT + (size_t)bz * NN * NP);
    __nv_bfloat16* attn = g_attnb + (size_t)bz * NN * NN;

    float* red = (float*)(smem + FRED_OFF);   // [64][4]
    float* m_s = (float*)(smem + FM_OFF);     // [64]

    // prologue: q tile (64x256B) + k tile 0 (128x256B)
    {
#pragma unroll
        for (int p = 0; p < 4; p++) {
            int idx = p * 256 + tid;
            int r = idx >> 4, ch = idx & 15;
            CP_ASYNC16(sb + FQ_OFF + SW2(r, ch), qg + (size_t)r * 256 + ch * 16);
        }
#pragma unroll
        for (int p = 0; p < 8; p++) {
            int idx = p * 256 + tid;
            int r = idx >> 4, ch = idx & 15;
            CP_ASYNC16(sb + FK_OFF + SW2(r, ch), kg + (size_t)r * 256 + ch * 16);
        }
        CP_COMMIT();
    }

    int a_r[2], b_r[2];
#pragma unroll
    for (int mt = 0; mt < 2; mt++) a_r[mt] = wm * 32 + mt * 16 + ((lane >> 3) & 1) * 8 + (lane & 7);
#pragma unroll
    for (int p = 0; p < 2; p++) b_r[p] = wn * 32 + p * 16 + ((lane >> 4) & 1) * 8 + (lane & 7);
    const int a_kc = (lane >> 4) & 1, b_kc = (lane >> 3) & 1;

    float rm[2][2] = {{-1e30f, -1e30f}, {-1e30f, -1e30f}};
    float rs[2][2] = {{0.f, 0.f}, {0.f, 0.f}};

#pragma unroll 1
    for (int tt = 0; tt < 64; tt++) {
        const int j = tt & 31;
        // prefetch next k tile
        if (tt + 1 < 64) {
            const int jn = (tt + 1) & 31;
            const uint32_t dK = sb + FK_OFF + ((tt + 1) & 1) * 32768;
            const char* src = kg + (size_t)jn * 128 * 256;
#pragma unroll
            for (int p = 0; p < 8; p++) {
                int idx = p * 256 + tid;
                int r = idx >> 4, ch = idx & 15;
                CP_ASYNC16(dK + SW2(r, ch), src + (size_t)r * 256 + ch * 16);
            }
            CP_COMMIT();
            CP_WAIT1();
        } else {
            CP_WAIT0();
        }

        if (tt == 32) {
            // finalize row max from pass-1 running max
#pragma unroll
            for (int mt = 0; mt < 2; mt++)
#pragma unroll
                for (int h = 0; h < 2; h++) {
                    float v = rm[mt][h];
                    v = fmaxf(v, __shfl_xor_sync(0xffffffffu, v, 1));
                    v = fmaxf(v, __shfl_xor_sync(0xffffffffu, v, 2));
                    if (tg == 0) red[(wm * 32 + mt * 16 + g + h * 8) * 4 + wn] = v;
                }
            __syncthreads();
            if (tid < 64) {
                float m = fmaxf(fmaxf(red[tid * 4 + 0], red[tid * 4 + 1]),
                                fmaxf(red[tid * 4 + 2], red[tid * 4 + 3]));
                m_s[tid] = m;
            }
        }
        __syncthreads();

        // E gemm 64x128, K=128
        const uint32_t Ksb = sb + FK_OFF + (tt & 1) * 32768;
        float acc[2][4][4];
#pragma unroll
        for (int a = 0; a < 2; a++)
#pragma unroll
            for (int bq = 0; bq < 4; bq++)
#pragma unroll
                for (int c = 0; c < 4; c++) acc[a][bq][c] = 0.f;

#pragma unroll
        for (int ks = 0; ks < 8; ks++) {
            uint32_t aF[2][4], bF[2][4];
#pragma unroll
            for (int mt = 0; mt < 2; mt++)
                ldsm4(aF[mt][0], aF[mt][1], aF[mt][2], aF[mt][3],
                      sb + FQ_OFF + SW2(a_r[mt], ks * 2 + a_kc));
#pragma unroll
            for (int p = 0; p < 2; p++)
                ldsm4(bF[p][0], bF[p][1], bF[p][2], bF[p][3],
                      Ksb + SW2(b_r[p], ks * 2 + b_kc));
#pragma unroll
            for (int mt = 0; mt < 2; mt++) {
                mma16816(acc[mt][0], aF[mt][0], aF[mt][1], aF[mt][2], aF[mt][3], bF[0][0], bF[0][1]);
                mma16816(acc[mt][1], aF[mt][0], aF[mt][1], aF[mt][2], aF[mt][3], bF[0][2], bF[0][3]);
                mma16816(acc[mt][2], aF[mt][0], aF[mt][1], aF[mt][2], aF[mt][3], bF[1][0], bF[1][1]);
                mma16816(acc[mt][3], aF[mt][0], aF[mt][1], aF[mt][2], aF[mt][3], bF[1][2], bF[1][3]);
            }
        }

        if (tt < 32) {
            // pass 1: running row max
#pragma unroll
            for (int mt = 0; mt < 2; mt++)
#pragma unroll
                for (int h = 0; h < 2; h++) {
                    float v = rm[mt][h];
#pragma unroll
                    for (int nt = 0; nt < 4; nt++) {
                        v = fmaxf(v, acc[mt][nt][h * 2 + 0]);
                        v = fmaxf(v, acc[mt][nt][h * 2 + 1]);
                    }
                    rm[mt][h] = v;
                }
        } else {
            // pass 2: P = exp(E - m), stage in smem, row-sum accumulate
#pragma unroll
            for (int mt = 0; mt < 2; mt++)
#pragma unroll
                for (int h = 0; h < 2; h++) {
                    const int il = wm * 32 + mt * 16 + g + h * 8;
                    const float m = m_s[il];
                    float s = rs[mt][h];
#pragma unroll
                    for (int nt = 0; nt < 4; nt++) {
                        float p0 = __expf(acc[mt][nt][h * 2 + 0] - m);
                        float p1 = __expf(acc[mt][nt][h * 2 + 1] - m);
                        s += p0 + p1;
                        const int jl = wn * 32 + nt * 8 + tg * 2;
                        __nv_bfloat162 pk;
                        pk.x = __float2bfloat16(p0);
                        pk.y = __float2bfloat16(p1);
                        uint32_t addr = sb + FP_OFF + il * 256 +
                                        ((((jl >> 3) ^ (il & 7))) * 16) + (jl & 7) * 2;
                        asm volatile("st.shared.b32 [%0], %1;" :: "r"(addr),
                                     "r"(*(uint32_t*)&pk) : "memory");
                    }
                    rs[mt][h] = s;
                }
            __syncthreads();
            // coalesced copy P -> global (64 rows x 128 bf16)
#pragma unroll
            for (int p = 0; p < 4; p++) {
                int idx = p * 256 + tid;
                int r = idx >> 4, ch = idx & 15;
                uint4 val = *(uint4*)(smem + FP_OFF + SW2(r, ch));
                *(uint4*)&attn[(size_t)(i0 + r) * NN + j * 128 + ch * 8] = val;
            }
        }
    }

    // finalize rowsum -> g_linv
#pragma unroll
    for (int mt = 0; mt < 2; mt++)
#pragma unroll
        for (int h = 0; h < 2; h++) {
            float s = rs[mt][h];
            s += __shfl_xor_sync(0xffffffffu, s, 1);
            s += __shfl_xor_sync(0xffffffffu, s, 2);
            if (tg == 0) red[(wm * 32 + mt * 16 + g + h * 8) * 4 + wn] = s;
        }
    __syncthreads();
    if (tid < 64) {
        float l = red[tid * 4 + 0] + red[tid * 4 + 1] + red[tid * 4 + 2] + red[tid * 4 + 3];
        g_linv[(size_t)bz * NN + i0 + tid] = 1.f / l;
    }
}

// ---------------------------------------------------------------------------
// out: O[c,i] = (sum_j v[c,j]*P[i,j]) * linv[i];  out = gamma*O + x.
// ---------------------------------------------------------------------------
__global__ __launch_bounds__(256)
void out_kernel(const float* __restrict__ gamma, const float* __restrict__ x,
                float* __restrict__ out)
{
    extern __shared__ __align__(1024) char smem[];
    const uint32_t sb = smem_u32(smem);
    const int tid = threadIdx.x;
    const int lane = tid & 31, wid = tid >> 5;
    const int wm = wid >> 2, wn = wid & 3;
    const int bz = blockIdx.z, c0 = blockIdx.x * 128, i0 = blockIdx.y * 128;

    const uint4* va = (const uint4*)(g_vb    + (size_t)bz * CC * NN);
    const uint4* aa = (const uint4*)(g_attnb + (size_t)bz * NN * NN);

    float acc[4][4][4];
#pragma unroll
    for (int i = 0; i < 4; i++)
#pragma unroll
        for (int j = 0; j < 4; j++)
#pragma unroll
            for (int k = 0; k < 4; k++) acc[i][j][k] = 0.f;

    gemm128x128<64>(sb, va, aa, NN / 8, NN / 8, c0, i0, acc);

    const float* linv = g_linv + (size_t)bz * NN;
    const int g = lane >> 2, tg = lane & 3;

    float li[4][2];
#pragma unroll
    for (int nt = 0; nt < 4; nt++) {
        int n = i0 + wn * 32 + nt * 8 + tg * 2;
        li[nt][0] = linv[n];
        li[nt][1] = linv[n + 1];
    }

#pragma unroll
    for (int mt = 0; mt < 4; mt++) {
#pragma unroll
        for (int half = 0; half < 2; half++) {
            int c = c0 + wm * 64 + mt * 16 + g + half * 8;
#pragma unroll
            for (int nt = 0; nt < 4; nt++) {
                int n = i0 + wn * 32 + nt * 8 + tg * 2;
                size_t gi = (size_t)c * NN + n;
                size_t bi = (size_t)bz * CC * NN + gi;
                float2 gm = *(const float2*)&gamma[gi];
                float2 xx = *(const float2*)&x[bi];
                float2 o;
                o.x = fmaf(gm.x, acc[mt][nt][half * 2 + 0] * li[nt][0], xx.x);
                o.y = fmaf(gm.y, acc[mt][nt][half * 2 + 1] * li[nt][1], xx.y);
                *(float2*)&out[bi] = o;
            }
        }
    }
}

// ---------------------------------------------------------------------------
extern "C" void kernel_launch(void* const* d_in, const int* in_sizes, int n_in,
                              void* d_out, int out_size)
{
    const float* x     = (const float*)d_in[0];
    const float* Wq    = (const float*)d_in[1];
    const float* Wk    = (const float*)d_in[2];
    const float* Wv    = (const float*)d_in[3];
    const float* sq    = (const float*)d_in[4];
    const float* bq    = (const float*)d_in[5];
    const float* sk    = (const float*)d_in[6];
    const float* bk    = (const float*)d_in[7];
    const float* sv    = (const float*)d_in[8];
    const float* bv    = (const float*)d_in[9];
    const float* gamma = (const float*)d_in[10];
    float* out = (float*)d_out;

    const int DSMEM = 65536;
    cudaFuncSetAttribute(proj_qk_kernel, cudaFuncAttributeMaxDynamicSharedMemorySize, DSMEM);
    cudaFuncSetAttribute(proj_v_kernel,  cudaFuncAttributeMaxDynamicSharedMemorySize, DSMEM);
    cudaFuncSetAttribute(out_kernel,     cudaFuncAttributeMaxDynamicSharedMemorySize, DSMEM);
    cudaFuncSetAttribute(energy_softmax_kernel,
                         cudaFuncAttributeMaxDynamicSharedMemorySize, FSMEM);

    dim3 blk(256);

    convert_w_kernel<<<(CC * CC + 2 * NP * CC) / 256, blk>>>(Wv, Wq, Wk);
    transpose_x_kernel<<<dim3(CC / 128, NN / 128, BB), blk>>>(x);

    proj_qk_kernel<<<dim3(NN / 128, 1, BB), blk, DSMEM>>>(sq, bq, 0);
    proj_qk_kernel<<<dim3(NN / 128, 1, BB), blk, DSMEM>>>(sk, bk, 1);
    proj_v_kernel<<<dim3(CC / 128, NN / 128, BB), blk, DSMEM>>>(sv, bv);

    energy_softmax_kernel<<<dim3(NN / 64, BB), blk, FSMEM>>>();

    out_kernel<<<dim3(CC / 128, NN / 128, BB), blk, DSMEM>>>(gamma, x, out);
}